// round 14
// baseline (speedup 1.0000x reference)
#include <cuda_runtime.h>
#include <cuda_bf16.h>
#include <cstdint>

#define THREADS 384
#define NW      12            // warps per CTA, each fully independent
#define TILE    16            // points per warp tile
#define RS_X    28            // x-stage row stride (u32 words)

// ---- smem layout (u32 units) ----
#define U_EBIAS  0                         // 8 cams x 128 floats (b0 + emb@W0[0:16])
#define U_BIAS1  1024                      // 128
#define U_BIAS2  1152                      // 8
#define U_BF0    1160                      // 16j*3s*32 uint4 = 6144 u32
#define U_BF1    (U_BF0 + 6144)            // 16j*8s*32 uint4 = 16384 u32
#define U_BF2    (U_BF1 + 16384)           // 8s*32 uint4 = 1024 u32
#define U_XBUF   (U_BF2 + 1024)            // 12 warps * 16*RS_X*2
#define U_TOTAL  (U_XBUF + NW*16*RS_X*2)   // 35464 u32 = 141856 B

__device__ __forceinline__ void mma_bf16(float c[4], const uint32_t a[4],
                                         uint32_t b0, uint32_t b1) {
    asm("mma.sync.aligned.m16n8k16.row.col.f32.bf16.bf16.f32 "
        "{%0,%1,%2,%3}, {%4,%5,%6,%7}, {%8,%9}, {%0,%1,%2,%3};"
        : "+f"(c[0]), "+f"(c[1]), "+f"(c[2]), "+f"(c[3])
        : "r"(a[0]), "r"(a[1]), "r"(a[2]), "r"(a[3]), "r"(b0), "r"(b1));
}
__device__ __forceinline__ uint32_t pack_rn_bf16x2(float lo_elem, float hi_elem) {
    uint32_t r;
    asm("cvt.rn.bf16x2.f32 %0, %1, %2;" : "=r"(r) : "f"(hi_elem), "f"(lo_elem));
    return r;
}
__device__ __forceinline__ void split_rn(float v, uint16_t& h, uint16_t& l) {
    __nv_bfloat16 bh = __float2bfloat16(v);
    float res = v - __bfloat162float(bh);
    __nv_bfloat16 bl = __float2bfloat16(res);
    h = __bfloat16_as_ushort(bh);
    l = __bfloat16_as_ushort(bl);
}

// relu(acc+bias) for 4-frag, split into hi (trunc) / lo (rn residual) bf16x2 regs
__device__ __forceinline__ void cvt_frag(const float* c, float bxA, float byA,
                                         float bxB, float byB,
                                         uint32_t& h01, uint32_t& h23,
                                         uint32_t& l01, uint32_t& l23) {
    float v0 = fmaxf(c[0] + bxA, 0.0f), v1 = fmaxf(c[1] + byA, 0.0f);
    float v2 = fmaxf(c[2] + bxB, 0.0f), v3 = fmaxf(c[3] + byB, 0.0f);
    uint32_t u0 = __float_as_uint(v0), u1 = __float_as_uint(v1);
    uint32_t u2 = __float_as_uint(v2), u3 = __float_as_uint(v3);
    h01 = __byte_perm(u0, u1, 0x7632);
    h23 = __byte_perm(u2, u3, 0x7632);
    float l0 = v0 - __uint_as_float(u0 & 0xFFFF0000u);
    float l1 = v1 - __uint_as_float(u1 & 0xFFFF0000u);
    float l2 = v2 - __uint_as_float(u2 & 0xFFFF0000u);
    float l3 = v3 - __uint_as_float(u3 & 0xFFFF0000u);
    l01 = pack_rn_bf16x2(l0, l1);
    l23 = pack_rn_bf16x2(l2, l3);
}

__global__ void __launch_bounds__(THREADS, 1) vdc_mlp_regpipe12_kernel(
    const float* __restrict__ features,     // [N, 32]
    const float* __restrict__ dirs,         // [C, N, 3]
    const float* __restrict__ embed_table,  // [1000, 16]
    const float* __restrict__ W0,           // [64, 128]
    const float* __restrict__ b0,
    const float* __restrict__ W1,           // [128, 128]
    const float* __restrict__ b1,
    const float* __restrict__ W2,           // [128, 3]
    const float* __restrict__ b2,
    const int*   __restrict__ embed_ids,    // [C]
    const int*   __restrict__ sh_degree_p,
    float*       __restrict__ out,          // [C, N, 3]
    int C, int N)
{
    extern __shared__ uint32_t sm[];
    float* EBIAS = (float*)(sm + U_EBIAS);   // [8][128]
    float* BIAS1 = (float*)(sm + U_BIAS1);
    float* BIAS2 = (float*)(sm + U_BIAS2);
    const uint4* BF0 = (const uint4*)(sm + U_BF0);
    const uint4* BF1 = (const uint4*)(sm + U_BF1);
    const uint4* BF2 = (const uint4*)(sm + U_BF2);

    const int tid = threadIdx.x;

    // ---------------- one-time staging ----------------
    for (int i = tid; i < 128; i += THREADS) BIAS1[i] = b1[i];
    if (tid < 8) BIAS2[tid] = (tid < 3) ? b2[tid] : 0.0f;

    const int ncb = (C < 8 ? C : 8);
    for (int i = tid; i < ncb * 128; i += THREADS) {
        int c = i >> 7, col = i & 127;
        const float* er = embed_table + (long)embed_ids[c] * 16;
        float s = b0[col];
        #pragma unroll
        for (int k = 0; k < 16; k++) s += __ldg(er + k) * W0[k * 128 + col];
        EBIAS[c * 128 + col] = s;
    }

    // BF0: layer0 B frags (inputs = feat32|sh16 -> W0 rows 16..63), KS=3, j 0..15
    for (int i = tid; i < 16 * 3 * 32; i += THREADS) {
        int lane = i & 31, js = i >> 5, s = js % 3, j = js / 3;
        int n = j * 8 + (lane >> 2), k0 = s * 16 + 2 * (lane & 3);
        uint16_t h[4], l[4];
        #pragma unroll
        for (int q = 0; q < 4; q++) {
            int k = k0 + (q >> 1) * 8 + (q & 1);
            split_rn(W0[(16 + k) * 128 + n], h[q], l[q]);
        }
        uint4 v;
        v.x = (uint32_t)h[0] | ((uint32_t)h[1] << 16);
        v.y = (uint32_t)h[2] | ((uint32_t)h[3] << 16);
        v.z = (uint32_t)l[0] | ((uint32_t)l[1] << 16);
        v.w = (uint32_t)l[2] | ((uint32_t)l[3] << 16);
        ((uint4*)(sm + U_BF0))[i] = v;
    }
    // BF1: layer1, KS=8, j 0..15
    for (int i = tid; i < 16 * 8 * 32; i += THREADS) {
        int lane = i & 31, js = i >> 5, s = js & 7, j = js >> 3;
        int n = j * 8 + (lane >> 2), k0 = s * 16 + 2 * (lane & 3);
        uint16_t h[4], l[4];
        #pragma unroll
        for (int q = 0; q < 4; q++) {
            int k = k0 + (q >> 1) * 8 + (q & 1);
            split_rn(W1[k * 128 + n], h[q], l[q]);
        }
        uint4 v;
        v.x = (uint32_t)h[0] | ((uint32_t)h[1] << 16);
        v.y = (uint32_t)h[2] | ((uint32_t)h[3] << 16);
        v.z = (uint32_t)l[0] | ((uint32_t)l[1] << 16);
        v.w = (uint32_t)l[2] | ((uint32_t)l[3] << 16);
        ((uint4*)(sm + U_BF1))[i] = v;
    }
    // BF2: layer2 (n padded to 8), KS=8
    for (int i = tid; i < 8 * 32; i += THREADS) {
        int lane = i & 31, s = i >> 5;
        int n = lane >> 2, k0 = s * 16 + 2 * (lane & 3);
        uint16_t h[4], l[4];
        #pragma unroll
        for (int q = 0; q < 4; q++) {
            int k = k0 + (q >> 1) * 8 + (q & 1);
            float w = (n < 3) ? W2[k * 3 + n] : 0.0f;
            split_rn(w, h[q], l[q]);
        }
        uint4 v;
        v.x = (uint32_t)h[0] | ((uint32_t)h[1] << 16);
        v.y = (uint32_t)h[2] | ((uint32_t)h[3] << 16);
        v.z = (uint32_t)l[0] | ((uint32_t)l[1] << 16);
        v.w = (uint32_t)l[2] | ((uint32_t)l[3] << 16);
        ((uint4*)(sm + U_BF2))[i] = v;
    }

    int deg = 3;
    if (sh_degree_p) deg = *sh_degree_p;
    const int nb_use = (deg + 1) * (deg + 1);
    __syncthreads();

    const int warp = tid >> 5;
    const int lane = tid & 31;
    const int r  = lane >> 2;
    const int cb = lane & 3;

    uint32_t* xh = sm + U_XBUF + warp * (2 * 16 * RS_X);
    uint32_t* xl = xh + 16 * RS_X;

    const int total  = C * N;
    const int ntiles = (total + TILE - 1) / TILE;

    for (int tile = blockIdx.x * NW + warp; tile < ntiles; tile += gridDim.x * NW) {
        const int tb = tile * TILE;
        __syncwarp();     // prior tile's x reads done before overwrite

        // -------- x-build: lane = (row = lane>>1, half = lane&1) --------
        {
            const int row  = lane >> 1;
            const int half = lane & 1;
            const int p = tb + row;
            float v[24];
            if (p < total) {
                const int c = p / N;
                const int n = p - c * N;
                const float4* fr = (const float4*)(features + (long)n * 32);
                if (half == 0) {
                    #pragma unroll
                    for (int q = 0; q < 6; q++) {
                        float4 f = __ldg(fr + q);
                        v[4*q+0]=f.x; v[4*q+1]=f.y; v[4*q+2]=f.z; v[4*q+3]=f.w;
                    }
                } else {
                    #pragma unroll
                    for (int q = 0; q < 2; q++) {
                        float4 f = __ldg(fr + 6 + q);
                        v[4*q+0]=f.x; v[4*q+1]=f.y; v[4*q+2]=f.z; v[4*q+3]=f.w;
                    }
                    const float dx = dirs[(long)p*3 + 0];
                    const float dy = dirs[(long)p*3 + 1];
                    const float dz = dirs[(long)p*3 + 2];
                    float nrm = sqrtf(dx*dx + dy*dy + dz*dz);
                    float inv = 1.0f / fmaxf(nrm, 1e-12f);
                    const float sx = dx*inv, sy = dy*inv, sz = dz*inv;
                    const float z2     = sz * sz;
                    const float fTmp0B = -1.092548430592079f * sz;
                    const float fC1    = sx*sx - sy*sy;
                    const float fS1    = 2.0f * sx * sy;
                    const float fTmp0C = -2.285228997322329f * z2 + 0.4570457994644658f;
                    const float fTmp1B = 1.445305721320277f * sz;
                    const float fC2    = sx*fC1 - sy*fS1;
                    const float fS2    = sx*fS1 + sy*fC1;
                    float sh[16];
                    sh[0]  = 0.2820947917738781f;
                    sh[1]  = -0.48860251190292f * sy;
                    sh[2]  =  0.48860251190292f * sz;
                    sh[3]  = -0.48860251190292f * sx;
                    sh[4]  =  0.5462742152960395f * fS1;
                    sh[5]  =  fTmp0B * sy;
                    sh[6]  =  0.9461746957575601f * z2 - 0.3153915652525201f;
                    sh[7]  =  fTmp0B * sx;
                    sh[8]  =  0.5462742152960395f * fC1;
                    sh[9]  = -0.5900435899266435f * fS2;
                    sh[10] =  fTmp1B * fS1;
                    sh[11] =  fTmp0C * sy;
                    sh[12] =  sz * (1.865881662950577f * z2 - 1.119528997770346f);
                    sh[13] =  fTmp0C * sx;
                    sh[14] =  fTmp1B * fC1;
                    sh[15] = -0.5900435899266435f * fC2;
                    #pragma unroll
                    for (int k = 0; k < 16; k++) v[8 + k] = (k < nb_use) ? sh[k] : 0.0f;
                }
            } else {
                #pragma unroll
                for (int k = 0; k < 24; k++) v[k] = 0.0f;
            }
            const int wbase = (lane >> 1) * RS_X + half * 12;
            #pragma unroll
            for (int w = 0; w < 12; w++) {
                float a = v[2*w], b = v[2*w+1];
                uint32_t ua = __float_as_uint(a), ub = __float_as_uint(b);
                xh[wbase + w] = __byte_perm(ua, ub, 0x7632);
                float la = a - __uint_as_float(ua & 0xFFFF0000u);
                float lb = b - __uint_as_float(ub & 0xFFFF0000u);
                xl[wbase + w] = pack_rn_bf16x2(la, lb);
            }
        }
        __syncwarp();

        // camera bias rows for this tile (cheap, reused in epilogue 0)
        const int pA = tb + r, pB = tb + r + 8;
        const float* eA = EBIAS + ((pA < total) ? (pA / N) : 0) * 128;
        const float* eB = EBIAS + ((pB < total) ? (pB / N) : 0) * 128;

        uint32_t A1H[32], A1L[32];     // layer-1 A fragments (built by epilogue 0)

        // -------- layer 0 (48 -> 128) in two j-halves of 8 col-tiles --------
        #pragma unroll
        for (int jh = 0; jh < 2; jh++) {
            float acc[32];
            #pragma unroll
            for (int i = 0; i < 32; i++) acc[i] = 0.0f;
            #pragma unroll
            for (int s = 0; s < 3; s++) {
                const int cw = s * 8 + cb;
                uint32_t AH[4], AL[4];
                AH[0] = xh[r * RS_X + cw];       AH[1] = xh[(r + 8) * RS_X + cw];
                AH[2] = xh[r * RS_X + cw + 4];   AH[3] = xh[(r + 8) * RS_X + cw + 4];
                AL[0] = xl[r * RS_X + cw];       AL[1] = xl[(r + 8) * RS_X + cw];
                AL[2] = xl[r * RS_X + cw + 4];   AL[3] = xl[(r + 8) * RS_X + cw + 4];
                #pragma unroll
                for (int jj = 0; jj < 8; jj++) {
                    const int j = jh * 8 + jj;
                    uint4 b = BF0[(j * 3 + s) * 32 + lane];
                    float* c = acc + jj * 4;
                    mma_bf16(c, AH, b.x, b.y);
                    mma_bf16(c, AH, b.z, b.w);
                    mma_bf16(c, AL, b.x, b.y);
                }
            }
            // epilogue 0 half: relu(acc + ebias) -> A1 frags for s = jh*4 .. jh*4+3
            #pragma unroll
            for (int jj = 0; jj < 8; jj++) {
                const int j = jh * 8 + jj;
                float2 bA = *(const float2*)(eA + j * 8 + 2 * cb);
                float2 bB = *(const float2*)(eB + j * 8 + 2 * cb);
                const int idx = (j >> 1) * 4 + (j & 1) * 2;
                cvt_frag(acc + jj * 4, bA.x, bA.y, bB.x, bB.y,
                         A1H[idx], A1H[idx + 1], A1L[idx], A1L[idx + 1]);
            }
        }

        // -------- layer 1 (128 -> 128) in two j-halves --------
        uint32_t A2H[32], A2L[32];
        #pragma unroll
        for (int jh = 0; jh < 2; jh++) {
            float acc[32];
            #pragma unroll
            for (int i = 0; i < 32; i++) acc[i] = 0.0f;
            #pragma unroll
            for (int s = 0; s < 8; s++) {
                #pragma unroll
                for (int jj = 0; jj < 8; jj++) {
                    const int j = jh * 8 + jj;
                    uint4 b = BF1[(j * 8 + s) * 32 + lane];
                    float* c = acc + jj * 4;
                    mma_bf16(c, A1H + s * 4, b.x, b.y);
                    mma_bf16(c, A1H + s * 4, b.z, b.w);
                    mma_bf16(c, A1L + s * 4, b.x, b.y);
                }
            }
            #pragma unroll
            for (int jj = 0; jj < 8; jj++) {
                const int j = jh * 8 + jj;
                float2 bb = *(const float2*)(BIAS1 + j * 8 + 2 * cb);
                const int idx = (j >> 1) * 4 + (j & 1) * 2;
                cvt_frag(acc + jj * 4, bb.x, bb.y, bb.x, bb.y,
                         A2H[idx], A2H[idx + 1], A2L[idx], A2L[idx + 1]);
            }
        }

        // -------- layer 2: 128 -> 3 (n padded to 8) --------
        float C2[4] = {0.f, 0.f, 0.f, 0.f};
        #pragma unroll
        for (int s = 0; s < 8; s++) {
            uint4 b = BF2[s * 32 + lane];
            mma_bf16(C2, A2H + s * 4, b.x, b.y);
            mma_bf16(C2, A2H + s * 4, b.z, b.w);
            mma_bf16(C2, A2L + s * 4, b.x, b.y);
        }

        // -------- output --------
        {
            const int p0 = tb + r;
            const int p1 = p0 + 8;
            if (cb == 0) {
                if (p0 < total) {
                    out[(long)p0*3 + 0] = C2[0] + BIAS2[0];
                    out[(long)p0*3 + 1] = C2[1] + BIAS2[1];
                }
                if (p1 < total) {
                    out[(long)p1*3 + 0] = C2[2] + BIAS2[0];
                    out[(long)p1*3 + 1] = C2[3] + BIAS2[1];
                }
            } else if (cb == 1) {
                if (p0 < total) out[(long)p0*3 + 2] = C2[0] + BIAS2[2];
                if (p1 < total) out[(long)p1*3 + 2] = C2[2] + BIAS2[2];
            }
        }
    }
}

extern "C" void kernel_launch(void* const* d_in, const int* in_sizes, int n_in,
                              void* d_out, int out_size)
{
    const float* features    = (const float*)d_in[0];
    const float* dirs        = (const float*)d_in[1];
    const float* embed_table = (const float*)d_in[2];
    const float* W0          = (const float*)d_in[3];
    const float* b0          = (const float*)d_in[4];
    const float* W1          = (const float*)d_in[5];
    const float* b1          = (const float*)d_in[6];
    const float* W2          = (const float*)d_in[7];
    const float* b2          = (const float*)d_in[8];
    const int*   embed_ids   = (const int*)d_in[9];
    const int*   sh_degree_p = (n_in > 10) ? (const int*)d_in[10] : nullptr;
    float* out = (float*)d_out;

    const int C = in_sizes[9];
    const int N = in_sizes[1] / (3 * C);
    const int total = C * N;
    const int ntiles = (total + TILE - 1) / TILE;
    const int cta_tiles = (ntiles + NW - 1) / NW;

    int dev = 0, sms = 148;
    cudaGetDevice(&dev);
    cudaDeviceGetAttribute(&sms, cudaDevAttrMultiProcessorCount, dev);
    int grid = sms < cta_tiles ? sms : cta_tiles;

    const size_t smem_bytes = (size_t)U_TOTAL * 4;
    cudaFuncSetAttribute(vdc_mlp_regpipe12_kernel,
                         cudaFuncAttributeMaxDynamicSharedMemorySize, (int)smem_bytes);

    vdc_mlp_regpipe12_kernel<<<grid, THREADS, smem_bytes>>>(
        features, dirs, embed_table, W0, b0, W1, b1, W2, b2,
        embed_ids, sh_degree_p, out, C, N);
}

// round 15
// speedup vs baseline: 1.0022x; 1.0022x over previous
#include <cuda_runtime.h>
#include <cuda_bf16.h>
#include <cstdint>

#define THREADS 384
#define NW      12            // warps per CTA, each fully independent
#define TILE    16            // points per warp tile
#define RS_X    28            // x-stage row stride (u32 words)

// ---- smem layout (u32 units) ----
#define U_EBIAS  0                         // 8 cams x 128 floats (b0 + emb@W0[0:16])
#define U_BIAS1  1024                      // 128
#define U_BIAS2  1152                      // 8
#define U_BF0    1160                      // 16j*3s*32 uint4 = 6144 u32
#define U_BF1    (U_BF0 + 6144)            // 16j*8s*32 uint4 = 16384 u32
#define U_BF2    (U_BF1 + 16384)           // 8s*32 uint4 = 1024 u32
#define U_XBUF   (U_BF2 + 1024)            // 12 warps * 16*RS_X*2
#define U_TOTAL  (U_XBUF + NW*16*RS_X*2)   // 35464 u32 = 141856 B

__device__ __forceinline__ void mma_bf16(float c[4], const uint32_t a[4],
                                         uint32_t b0, uint32_t b1) {
    asm("mma.sync.aligned.m16n8k16.row.col.f32.bf16.bf16.f32 "
        "{%0,%1,%2,%3}, {%4,%5,%6,%7}, {%8,%9}, {%0,%1,%2,%3};"
        : "+f"(c[0]), "+f"(c[1]), "+f"(c[2]), "+f"(c[3])
        : "r"(a[0]), "r"(a[1]), "r"(a[2]), "r"(a[3]), "r"(b0), "r"(b1));
}
__device__ __forceinline__ uint32_t pack_rn_bf16x2(float lo_elem, float hi_elem) {
    uint32_t r;
    asm("cvt.rn.bf16x2.f32 %0, %1, %2;" : "=r"(r) : "f"(hi_elem), "f"(lo_elem));
    return r;
}
__device__ __forceinline__ void split_rn(float v, uint16_t& h, uint16_t& l) {
    __nv_bfloat16 bh = __float2bfloat16(v);
    float res = v - __bfloat162float(bh);
    __nv_bfloat16 bl = __float2bfloat16(res);
    h = __bfloat16_as_ushort(bh);
    l = __bfloat16_as_ushort(bl);
}

// relu(acc+bias) for 4-frag, split into hi (trunc) / lo (rn residual) bf16x2 regs
__device__ __forceinline__ void cvt_frag(const float* c, float bxA, float byA,
                                         float bxB, float byB,
                                         uint32_t& h01, uint32_t& h23,
                                         uint32_t& l01, uint32_t& l23) {
    float v0 = fmaxf(c[0] + bxA, 0.0f), v1 = fmaxf(c[1] + byA, 0.0f);
    float v2 = fmaxf(c[2] + bxB, 0.0f), v3 = fmaxf(c[3] + byB, 0.0f);
    uint32_t u0 = __float_as_uint(v0), u1 = __float_as_uint(v1);
    uint32_t u2 = __float_as_uint(v2), u3 = __float_as_uint(v3);
    h01 = __byte_perm(u0, u1, 0x7632);
    h23 = __byte_perm(u2, u3, 0x7632);
    float l0 = v0 - __uint_as_float(u0 & 0xFFFF0000u);
    float l1 = v1 - __uint_as_float(u1 & 0xFFFF0000u);
    float l2 = v2 - __uint_as_float(u2 & 0xFFFF0000u);
    float l3 = v3 - __uint_as_float(u3 & 0xFFFF0000u);
    l01 = pack_rn_bf16x2(l0, l1);
    l23 = pack_rn_bf16x2(l2, l3);
}

__global__ void __launch_bounds__(THREADS, 1) vdc_mlp_regpipe12_kernel(
    const float* __restrict__ features,     // [N, 32]
    const float* __restrict__ dirs,         // [C, N, 3]
    const float* __restrict__ embed_table,  // [1000, 16]
    const float* __restrict__ W0,           // [64, 128]
    const float* __restrict__ b0,
    const float* __restrict__ W1,           // [128, 128]
    const float* __restrict__ b1,
    const float* __restrict__ W2,           // [128, 3]
    const float* __restrict__ b2,
    const int*   __restrict__ embed_ids,    // [C]
    const int*   __restrict__ sh_degree_p,
    float*       __restrict__ out,          // [C, N, 3]
    int C, int N)
{
    extern __shared__ uint32_t sm[];
    float* EBIAS = (float*)(sm + U_EBIAS);   // [8][128]
    float* BIAS1 = (float*)(sm + U_BIAS1);
    float* BIAS2 = (float*)(sm + U_BIAS2);
    const uint4* BF0 = (const uint4*)(sm + U_BF0);
    const uint4* BF1 = (const uint4*)(sm + U_BF1);
    const uint4* BF2 = (const uint4*)(sm + U_BF2);

    const int tid = threadIdx.x;

    // ---------------- one-time staging ----------------
    for (int i = tid; i < 128; i += THREADS) BIAS1[i] = b1[i];
    if (tid < 8) BIAS2[tid] = (tid < 3) ? b2[tid] : 0.0f;

    const int ncb = (C < 8 ? C : 8);
    for (int i = tid; i < ncb * 128; i += THREADS) {
        int c = i >> 7, col = i & 127;
        const float* er = embed_table + (long)embed_ids[c] * 16;
        float s = b0[col];
        #pragma unroll
        for (int k = 0; k < 16; k++) s += __ldg(er + k) * W0[k * 128 + col];
        EBIAS[c * 128 + col] = s;
    }

    // BF0: layer0 B frags (inputs = feat32|sh16 -> W0 rows 16..63), KS=3, j 0..15
    for (int i = tid; i < 16 * 3 * 32; i += THREADS) {
        int lane = i & 31, js = i >> 5, s = js % 3, j = js / 3;
        int n = j * 8 + (lane >> 2), k0 = s * 16 + 2 * (lane & 3);
        uint16_t h[4], l[4];
        #pragma unroll
        for (int q = 0; q < 4; q++) {
            int k = k0 + (q >> 1) * 8 + (q & 1);
            split_rn(W0[(16 + k) * 128 + n], h[q], l[q]);
        }
        uint4 v;
        v.x = (uint32_t)h[0] | ((uint32_t)h[1] << 16);
        v.y = (uint32_t)h[2] | ((uint32_t)h[3] << 16);
        v.z = (uint32_t)l[0] | ((uint32_t)l[1] << 16);
        v.w = (uint32_t)l[2] | ((uint32_t)l[3] << 16);
        ((uint4*)(sm + U_BF0))[i] = v;
    }
    // BF1: layer1, KS=8, j 0..15
    for (int i = tid; i < 16 * 8 * 32; i += THREADS) {
        int lane = i & 31, js = i >> 5, s = js & 7, j = js >> 3;
        int n = j * 8 + (lane >> 2), k0 = s * 16 + 2 * (lane & 3);
        uint16_t h[4], l[4];
        #pragma unroll
        for (int q = 0; q < 4; q++) {
            int k = k0 + (q >> 1) * 8 + (q & 1);
            split_rn(W1[k * 128 + n], h[q], l[q]);
        }
        uint4 v;
        v.x = (uint32_t)h[0] | ((uint32_t)h[1] << 16);
        v.y = (uint32_t)h[2] | ((uint32_t)h[3] << 16);
        v.z = (uint32_t)l[0] | ((uint32_t)l[1] << 16);
        v.w = (uint32_t)l[2] | ((uint32_t)l[3] << 16);
        ((uint4*)(sm + U_BF1))[i] = v;
    }
    // BF2: layer2 (n padded to 8), KS=8
    for (int i = tid; i < 8 * 32; i += THREADS) {
        int lane = i & 31, s = i >> 5;
        int n = lane >> 2, k0 = s * 16 + 2 * (lane & 3);
        uint16_t h[4], l[4];
        #pragma unroll
        for (int q = 0; q < 4; q++) {
            int k = k0 + (q >> 1) * 8 + (q & 1);
            float w = (n < 3) ? W2[k * 3 + n] : 0.0f;
            split_rn(w, h[q], l[q]);
        }
        uint4 v;
        v.x = (uint32_t)h[0] | ((uint32_t)h[1] << 16);
        v.y = (uint32_t)h[2] | ((uint32_t)h[3] << 16);
        v.z = (uint32_t)l[0] | ((uint32_t)l[1] << 16);
        v.w = (uint32_t)l[2] | ((uint32_t)l[3] << 16);
        ((uint4*)(sm + U_BF2))[i] = v;
    }

    int deg = 3;
    if (sh_degree_p) deg = *sh_degree_p;
    const int nb_use = (deg + 1) * (deg + 1);
    __syncthreads();

    const int warp = tid >> 5;
    const int lane = tid & 31;
    const int r  = lane >> 2;
    const int cb = lane & 3;

    uint32_t* xh = sm + U_XBUF + warp * (2 * 16 * RS_X);
    uint32_t* xl = xh + 16 * RS_X;

    const int total  = C * N;
    const int ntiles = (total + TILE - 1) / TILE;

    for (int tile = blockIdx.x * NW + warp; tile < ntiles; tile += gridDim.x * NW) {
        const int tb = tile * TILE;
        __syncwarp();     // prior tile's x reads done before overwrite

        // -------- x-build: lane = (row = lane>>1, half = lane&1) --------
        {
            const int row  = lane >> 1;
            const int half = lane & 1;
            const int p = tb + row;
            float v[24];
            if (p < total) {
                const int c = p / N;
                const int n = p - c * N;
                const float4* fr = (const float4*)(features + (long)n * 32);
                if (half == 0) {
                    #pragma unroll
                    for (int q = 0; q < 6; q++) {
                        float4 f = __ldg(fr + q);
                        v[4*q+0]=f.x; v[4*q+1]=f.y; v[4*q+2]=f.z; v[4*q+3]=f.w;
                    }
                } else {
                    #pragma unroll
                    for (int q = 0; q < 2; q++) {
                        float4 f = __ldg(fr + 6 + q);
                        v[4*q+0]=f.x; v[4*q+1]=f.y; v[4*q+2]=f.z; v[4*q+3]=f.w;
                    }
                    const float dx = dirs[(long)p*3 + 0];
                    const float dy = dirs[(long)p*3 + 1];
                    const float dz = dirs[(long)p*3 + 2];
                    float nrm = sqrtf(dx*dx + dy*dy + dz*dz);
                    float inv = 1.0f / fmaxf(nrm, 1e-12f);
                    const float sx = dx*inv, sy = dy*inv, sz = dz*inv;
                    const float z2     = sz * sz;
                    const float fTmp0B = -1.092548430592079f * sz;
                    const float fC1    = sx*sx - sy*sy;
                    const float fS1    = 2.0f * sx * sy;
                    const float fTmp0C = -2.285228997322329f * z2 + 0.4570457994644658f;
                    const float fTmp1B = 1.445305721320277f * sz;
                    const float fC2    = sx*fC1 - sy*fS1;
                    const float fS2    = sx*fS1 + sy*fC1;
                    float sh[16];
                    sh[0]  = 0.2820947917738781f;
                    sh[1]  = -0.48860251190292f * sy;
                    sh[2]  =  0.48860251190292f * sz;
                    sh[3]  = -0.48860251190292f * sx;
                    sh[4]  =  0.5462742152960395f * fS1;
                    sh[5]  =  fTmp0B * sy;
                    sh[6]  =  0.9461746957575601f * z2 - 0.3153915652525201f;
                    sh[7]  =  fTmp0B * sx;
                    sh[8]  =  0.5462742152960395f * fC1;
                    sh[9]  = -0.5900435899266435f * fS2;
                    sh[10] =  fTmp1B * fS1;
                    sh[11] =  fTmp0C * sy;
                    sh[12] =  sz * (1.865881662950577f * z2 - 1.119528997770346f);
                    sh[13] =  fTmp0C * sx;
                    sh[14] =  fTmp1B * fC1;
                    sh[15] = -0.5900435899266435f * fC2;
                    #pragma unroll
                    for (int k = 0; k < 16; k++) v[8 + k] = (k < nb_use) ? sh[k] : 0.0f;
                }
            } else {
                #pragma unroll
                for (int k = 0; k < 24; k++) v[k] = 0.0f;
            }
            const int wbase = (lane >> 1) * RS_X + half * 12;
            #pragma unroll
            for (int w = 0; w < 12; w++) {
                float a = v[2*w], b = v[2*w+1];
                uint32_t ua = __float_as_uint(a), ub = __float_as_uint(b);
                xh[wbase + w] = __byte_perm(ua, ub, 0x7632);
                float la = a - __uint_as_float(ua & 0xFFFF0000u);
                float lb = b - __uint_as_float(ub & 0xFFFF0000u);
                xl[wbase + w] = pack_rn_bf16x2(la, lb);
            }
        }
        __syncwarp();

        // camera bias rows for this tile (cheap, reused in epilogue 0)
        const int pA = tb + r, pB = tb + r + 8;
        const float* eA = EBIAS + ((pA < total) ? (pA / N) : 0) * 128;
        const float* eB = EBIAS + ((pB < total) ? (pB / N) : 0) * 128;

        uint32_t A1H[32], A1L[32];     // layer-1 A fragments (built by epilogue 0)

        // -------- layer 0 (48 -> 128) in two j-halves of 8 col-tiles --------
        #pragma unroll
        for (int jh = 0; jh < 2; jh++) {
            float acc[32];
            #pragma unroll
            for (int i = 0; i < 32; i++) acc[i] = 0.0f;
            #pragma unroll
            for (int s = 0; s < 3; s++) {
                const int cw = s * 8 + cb;
                uint32_t AH[4], AL[4];
                AH[0] = xh[r * RS_X + cw];       AH[1] = xh[(r + 8) * RS_X + cw];
                AH[2] = xh[r * RS_X + cw + 4];   AH[3] = xh[(r + 8) * RS_X + cw + 4];
                AL[0] = xl[r * RS_X + cw];       AL[1] = xl[(r + 8) * RS_X + cw];
                AL[2] = xl[r * RS_X + cw + 4];   AL[3] = xl[(r + 8) * RS_X + cw + 4];
                #pragma unroll
                for (int jj = 0; jj < 8; jj++) {
                    const int j = jh * 8 + jj;
                    uint4 b = BF0[(j * 3 + s) * 32 + lane];
                    float* c = acc + jj * 4;
                    mma_bf16(c, AH, b.x, b.y);
                    mma_bf16(c, AH, b.z, b.w);
                    mma_bf16(c, AL, b.x, b.y);
                }
            }
            // epilogue 0 half: relu(acc + ebias) -> A1 frags for s = jh*4 .. jh*4+3
            #pragma unroll
            for (int jj = 0; jj < 8; jj++) {
                const int j = jh * 8 + jj;
                float2 bA = *(const float2*)(eA + j * 8 + 2 * cb);
                float2 bB = *(const float2*)(eB + j * 8 + 2 * cb);
                const int idx = (j >> 1) * 4 + (j & 1) * 2;
                cvt_frag(acc + jj * 4, bA.x, bA.y, bB.x, bB.y,
                         A1H[idx], A1H[idx + 1], A1L[idx], A1L[idx + 1]);
            }
        }

        // -------- layer 1 (128 -> 128) in two j-halves --------
        uint32_t A2H[32], A2L[32];
        #pragma unroll
        for (int jh = 0; jh < 2; jh++) {
            float acc[32];
            #pragma unroll
            for (int i = 0; i < 32; i++) acc[i] = 0.0f;
            #pragma unroll
            for (int s = 0; s < 8; s++) {
                #pragma unroll
                for (int jj = 0; jj < 8; jj++) {
                    const int j = jh * 8 + jj;
                    uint4 b = BF1[(j * 8 + s) * 32 + lane];
                    float* c = acc + jj * 4;
                    mma_bf16(c, A1H + s * 4, b.x, b.y);
                    mma_bf16(c, A1H + s * 4, b.z, b.w);
                    mma_bf16(c, A1L + s * 4, b.x, b.y);
                }
            }
            #pragma unroll
            for (int jj = 0; jj < 8; jj++) {
                const int j = jh * 8 + jj;
                float2 bb = *(const float2*)(BIAS1 + j * 8 + 2 * cb);
                const int idx = (j >> 1) * 4 + (j & 1) * 2;
                cvt_frag(acc + jj * 4, bb.x, bb.y, bb.x, bb.y,
                         A2H[idx], A2H[idx + 1], A2L[idx], A2L[idx + 1]);
            }
        }

        // -------- layer 2: 128 -> 3 (n padded to 8) --------
        float C2[4] = {0.f, 0.f, 0.f, 0.f};
        #pragma unroll
        for (int s = 0; s < 8; s++) {
            uint4 b = BF2[s * 32 + lane];
            mma_bf16(C2, A2H + s * 4, b.x, b.y);
            mma_bf16(C2, A2H + s * 4, b.z, b.w);
            mma_bf16(C2, A2L + s * 4, b.x, b.y);
        }

        // -------- output --------
        {
            const int p0 = tb + r;
            const int p1 = p0 + 8;
            if (cb == 0) {
                if (p0 < total) {
                    out[(long)p0*3 + 0] = C2[0] + BIAS2[0];
                    out[(long)p0*3 + 1] = C2[1] + BIAS2[1];
                }
                if (p1 < total) {
                    out[(long)p1*3 + 0] = C2[2] + BIAS2[0];
                    out[(long)p1*3 + 1] = C2[3] + BIAS2[1];
                }
            } else if (cb == 1) {
                if (p0 < total) out[(long)p0*3 + 2] = C2[0] + BIAS2[2];
                if (p1 < total) out[(long)p1*3 + 2] = C2[2] + BIAS2[2];
            }
        }
    }
}

extern "C" void kernel_launch(void* const* d_in, const int* in_sizes, int n_in,
                              void* d_out, int out_size)
{
    const float* features    = (const float*)d_in[0];
    const float* dirs        = (const float*)d_in[1];
    const float* embed_table = (const float*)d_in[2];
    const float* W0          = (const float*)d_in[3];
    const float* b0          = (const float*)d_in[4];
    const float* W1          = (const float*)d_in[5];
    const float* b1          = (const float*)d_in[6];
    const float* W2          = (const float*)d_in[7];
    const float* b2          = (const float*)d_in[8];
    const int*   embed_ids   = (const int*)d_in[9];
    const int*   sh_degree_p = (n_in > 10) ? (const int*)d_in[10] : nullptr;
    float* out = (float*)d_out;

    const int C = in_sizes[9];
    const int N = in_sizes[1] / (3 * C);
    const int total = C * N;
    const int ntiles = (total + TILE - 1) / TILE;
    const int cta_tiles = (ntiles + NW - 1) / NW;

    int dev = 0, sms = 148;
    cudaGetDevice(&dev);
    cudaDeviceGetAttribute(&sms, cudaDevAttrMultiProcessorCount, dev);
    int grid = sms < cta_tiles ? sms : cta_tiles;

    const size_t smem_bytes = (size_t)U_TOTAL * 4;
    cudaFuncSetAttribute(vdc_mlp_regpipe12_kernel,
                         cudaFuncAttributeMaxDynamicSharedMemorySize, (int)smem_bytes);

    vdc_mlp_regpipe12_kernel<<<grid, THREADS, smem_bytes>>>(
        features, dirs, embed_table, W0, b0, W1, b1, W2, b2,
        embed_ids, sh_degree_p, out, C, N);
}